// round 17
// baseline (speedup 1.0000x reference)
#include <cuda_runtime.h>

// ---------------------------------------------------------------------------
// Elman RNN (relu), B=64, T=512, I=64, H=1024, O=64
// out = [ hidden_list (B,T,H) | output_list (B,T,O) | h_last (1,B,H) ]
// ---------------------------------------------------------------------------

#define B_   64
#define T_   512
#define I_   64
#define H_   1024
#define O_   64

#define HID_OFF  0
#define OUT_OFF  (B_ * T_ * H_)              // 33554432
#define HL_OFF   (OUT_OFF + B_ * T_ * O_)    // 35651584

#define NBLK 128        // persistent blocks (1/SM)
#define TB   512        // 16 warps: warps 0-7 = group 2g, 8-15 = group 2g+1

// SMEM strides (floats)
#define CH    34        // K-chunk of 32 floats + 2 pad
#define HRow  1090      // W col row stride / h row stride
#define WQ    (8 * HRow + 8)    // 8728: W col-octet skew ({0,96,64,32} mod 128)
#define HHALF (8 * HRow)        // h region per half: 8 rows
#define PS    9         // psm region stride (8 vals + 1 pad; 9 coprime 32)
#define PHALF (8 * 32 * PS)     // psm per half = 2304 floats

// per-(group,block) flags (128B stride); 8 groups now
__device__ unsigned g_flag[8][32][32];

typedef unsigned long long ull;
typedef ulonglong2 ull2;

__device__ __forceinline__ ull f2fma(ull a, ull b, ull c) {
    ull d;
    asm("fma.rn.f32x2 %0, %1, %2, %3;" : "=l"(d) : "l"(a), "l"(b), "l"(c));
    return d;
}
__device__ __forceinline__ float pairsum(ull a) {
    float lo = __uint_as_float((unsigned)(a & 0xffffffffull));
    float hi = __uint_as_float((unsigned)(a >> 32));
    return lo + hi;
}
__device__ __forceinline__ unsigned ld_acq(unsigned* p) {
    unsigned v;
    asm volatile("ld.acquire.gpu.u32 %0, [%1];" : "=r"(v) : "l"(p) : "memory");
    return v;
}
__device__ __forceinline__ void st_rel(unsigned* p, unsigned v) {
    asm volatile("st.release.gpu.u32 [%0], %1;" :: "l"(p), "r"(v) : "memory");
}

// ---------------------------------------------------------------------------
// Kernel A: xw[bt][h] = x[bt]·W_ih[h] + b_ih[h] + b_hh[h]  -> hidden region
// 128x64 tile, 8x4 f32x2 micro-tile. Block (0,0) zeroes flags.
// ---------------------------------------------------------------------------
__global__ void __launch_bounds__(256) xw_kernel(
    const float* __restrict__ x, const float* __restrict__ Wih,
    const float* __restrict__ bih, const float* __restrict__ bhh,
    float* __restrict__ hid_out)
{
    extern __shared__ float axw[];
    float* xs = axw;                 // 128 rows x 66
    float* ws = axw + 128 * 66;      // 64 rows x 66

    const int tid = threadIdx.x;
    const int hb  = blockIdx.x * 64;
    const int btb = blockIdx.y * 128;

    if (blockIdx.x == 0 && blockIdx.y == 0) {
        #pragma unroll
        for (int i = tid; i < 8 * 32 * 32; i += 256)
            ((unsigned*)g_flag)[i] = 0;
    }

    const float2* x2 = (const float2*)x;
    const float2* w2 = (const float2*)Wih;
    #pragma unroll
    for (int k = 0; k < 16; ++k) {
        int idx = k * 256 + tid;
        int r = idx >> 5, q = idx & 31;
        *(float2*)&xs[r * 66 + 2 * q] = x2[(btb + r) * 32 + q];
    }
    #pragma unroll
    for (int k = 0; k < 8; ++k) {
        int idx = k * 256 + tid;
        int r = idx >> 5, q = idx & 31;
        *(float2*)&ws[r * 66 + 2 * q] = w2[(hb + r) * 32 + q];
    }
    __syncthreads();

    const int tx = tid & 15, ty = tid >> 4;
    ull acc[8][4];
    #pragma unroll
    for (int i = 0; i < 8; ++i)
        #pragma unroll
        for (int j = 0; j < 4; ++j) acc[i][j] = 0ull;

    #pragma unroll 4
    for (int k2 = 0; k2 < 32; ++k2) {
        ull a[8], b[4];
        #pragma unroll
        for (int i = 0; i < 8; ++i)
            a[i] = *(const ull*)&xs[(ty + 16 * i) * 66 + 2 * k2];
        #pragma unroll
        for (int j = 0; j < 4; ++j)
            b[j] = *(const ull*)&ws[(tx + 16 * j) * 66 + 2 * k2];
        #pragma unroll
        for (int i = 0; i < 8; ++i)
            #pragma unroll
            for (int j = 0; j < 4; ++j)
                acc[i][j] = f2fma(a[i], b[j], acc[i][j]);
    }

    #pragma unroll
    for (int j = 0; j < 4; ++j) {
        int h = hb + tx + 16 * j;
        float bb = bih[h] + bhh[h];
        #pragma unroll
        for (int i = 0; i < 8; ++i) {
            int bt = btb + ty + 16 * i;
            hid_out[bt * H_ + h] = pairsum(acc[i][j]) + bb;
        }
    }
}

// ---------------------------------------------------------------------------
// Kernel B: persistent recurrence, TWO independent groups per block.
// 128 blocks = 4 group-pairs x 32 col-groups. 512 threads:
// half = tid>>8; group = 2*pair + half (8 groups of 8 batches); W shared.
// Per half (8 warps): warp p owns K-chunks 4p..4p+3 (polls + stages them);
// lane (ko=lane&7 -> 16-K subchunk, t=lane>>3 -> col octet) computes an
// 8x8 f2fma tile (8 batches x 8 cols); 3-round ko-butterfly -> lane holds
// outputs [8ko,8ko+8) of tile t; partials -> skewed psm; half-scoped
// bar.sync; 8-way q reduce; relu epilogue; half bar; per-half flag release.
// The two halves stall independently -> each hides the other's tail.
// ---------------------------------------------------------------------------
__global__ void __launch_bounds__(TB, 1) rnn_recur(
    const float* __restrict__ hid_in,
    const float* __restrict__ Whh,
    float* __restrict__ out)
{
    extern __shared__ float sm[];
    float* wsm = sm;                       // 4 octet regions x WQ  (139,648 B)
    float* hsm = sm + 4 * WQ;              // 2 halves x 8 x HRow   (69,760 B)
    float* psm = sm + 4 * WQ + 2 * HHALF;  // 2 halves x 2304       (18,432 B)

    const int tid  = threadIdx.x;
    const int pair = blockIdx.x >> 5;      // 0..3
    const int ci   = blockIdx.x & 31;
    const int c0   = ci * 32;

    const int lane = tid & 31;
    const int w    = tid >> 5;             // 0..15
    const int half = w >> 3;               // 0 or 1
    const int p    = w & 7;                // warp-in-half: K quad owner
    const int ko   = lane & 7;             // 16-K subchunk within quad
    const int t    = lane >> 3;            // col octet 0..3

    const int group = pair * 2 + half;
    const int b0    = group * 8;
    const int tid_h = tid & 255;

    float* hsm_h = hsm + half * HHALF;
    float* psm_h = psm + half * PHALF;

    // ---- stage W_hh slice once: rows c0..c0+31, skewed octet layout ----
    const float2* W2 = (const float2*)Whh;
    #pragma unroll 4
    for (int i = tid; i < 32 * 512; i += TB) {
        int r = i >> 9, q = i & 511;
        *(float2*)&wsm[(r >> 3) * WQ + (r & 7) * HRow + (q >> 4) * CH + (q & 15) * 2] =
            __ldg(&W2[(c0 + r) * 512 + q]);
    }
    __syncthreads();

    const float* hb_ = hsm_h + (4 * p + (ko >> 1)) * CH + (ko & 1) * 16;
    const float* wb_ = wsm + t * WQ + (4 * p + (ko >> 1)) * CH + (ko & 1) * 16;

    float* hid_out = out + HID_OFF;
    float* hlast   = out + HL_OFF;

    // epilogue mapping: thread tid_h owns output o = tid_h (batch o>>5, col o&31)
    const int eb  = tid_h >> 5;
    const int ecl = tid_h & 31;
    const int gb  = b0 + eb;
    const int gc  = c0 + ecl;

    // psm write base: region n = 4*ko + t within q = p
    float* pw = psm_h + (p * 32 + 4 * ko + t) * PS;
    // psm read base offsets for output o: region (q*32 + 4*(o>>5) + ((o>>3)&3)),
    // element o&7
    const int rdn = 4 * eb + ((ecl >> 3) & 3);
    const int rdv = ecl & 7;

    // staging mapping: lane -> (cc = lane>>3 chunk-in-quad, f4 = lane&7)
    const int st_cc = lane >> 3;
    const int st_f4 = lane & 7;

    const int bar_mid = 1 + half;      // 1 or 2
    const int bar_epi = 3 + half;      // 3 or 4

    #pragma unroll 1
    for (int s = 0; s < T_; ++s) {
        // prefetch xw for this thread's output (own location, safe early)
        float xw = __ldcg(&hid_out[((size_t)gb * T_ + s) * H_ + gc]);

        // ---- per-warp parallel poll: producers 4p..4p+3 + own flag ----
        if (s > 0) {
            if (lane < 4) {
                unsigned* fp = &g_flag[group][4 * p + lane][0];
                while ((int)(ld_acq(fp) - (unsigned)s) < 0) { }
            } else if (lane == 4) {
                unsigned* fp = &g_flag[group][ci][0];
                while ((int)(ld_acq(fp) - (unsigned)s) < 0) { }
            }
            __syncwarp();
        }

        // ---- stage own quad: rows 0..7, chunks 4p..4p+3 ----
        const float4* hsrc;
        size_t rstr;
        if (s == 0) {
            hsrc = (const float4*)hid_in + (size_t)b0 * 256;
            rstr = 256;
        } else {
            hsrc = (const float4*)hid_out + ((size_t)b0 * 512 + (s - 1)) * 256;
            rstr = (size_t)512 * 256;
        }
        #pragma unroll
        for (int r = 0; r < 8; ++r) {
            float4 v = __ldcg(&hsrc[r * rstr + (4 * p + st_cc) * 8 + st_f4]);
            float* dst = &hsm_h[r * HRow + (4 * p + st_cc) * CH + st_f4 * 4];
            *(float2*)dst       = make_float2(v.x, v.y);
            *(float2*)(dst + 2) = make_float2(v.z, v.w);
        }
        __syncwarp();       // own warp staged own quad -> FMA may start

        // ---- 8x8 tile over private 16-K subchunk ----
        ull acc[64];
        #pragma unroll
        for (int i = 0; i < 64; ++i) acc[i] = 0ull;

        #pragma unroll
        for (int k2 = 0; k2 < 8; ++k2) {
            ull hv[8];
            #pragma unroll
            for (int i = 0; i < 8; ++i)
                hv[i] = *(const ull*)(hb_ + i * HRow + k2 * 2);
            ull wv[4];
            #pragma unroll
            for (int j = 0; j < 4; ++j)
                wv[j] = *(const ull*)(wb_ + j * HRow + k2 * 2);
            #pragma unroll
            for (int i = 0; i < 8; ++i)
                #pragma unroll
                for (int j = 0; j < 4; ++j)
                    acc[i * 8 + j] = f2fma(hv[i], wv[j], acc[i * 8 + j]);
            #pragma unroll
            for (int j = 0; j < 4; ++j)
                wv[j] = *(const ull*)(wb_ + (j + 4) * HRow + k2 * 2);
            #pragma unroll
            for (int i = 0; i < 8; ++i)
                #pragma unroll
                for (int j = 0; j < 4; ++j)
                    acc[i * 8 + j + 4] = f2fma(hv[i], wv[j], acc[i * 8 + j + 4]);
        }

        // ---- pairsum then 3-round butterfly over ko (masks 4,2,1) ----
        float vals[64];
        #pragma unroll
        for (int v = 0; v < 64; ++v) vals[v] = pairsum(acc[v]);

        #pragma unroll
        for (int m = 4, cnt = 32; m >= 1; m >>= 1, cnt >>= 1) {
            bool up = (lane & m) != 0;
            #pragma unroll
            for (int i = 0; i < 32; ++i) {
                if (i >= cnt) break;
                float send = up ? vals[i] : vals[i + cnt];
                float keep = up ? vals[i + cnt] : vals[i];
                float recv = __shfl_xor_sync(0xffffffffu, send, m);
                vals[i] = keep + recv;
            }
        }
        // lane holds vals[0..7] = outputs [8*ko, 8*ko+8) of tile t
        // (= batch ko, cols 8t..8t+7), partial over warp's 128-K range

        // ---- write partials to skewed psm region ----
        #pragma unroll
        for (int v = 0; v < 8; ++v)
            pw[v] = vals[v];

        asm volatile("bar.sync %0, 256;" :: "r"(bar_mid) : "memory");

        // ---- final reduce: 8 warp-partials for own output ----
        float sum = 0.0f;
        #pragma unroll
        for (int q = 0; q < 8; ++q)
            sum += psm_h[(q * 32 + rdn) * PS + rdv];

        float rr = fmaxf(xw + sum, 0.0f);
        hid_out[((size_t)gb * T_ + s) * H_ + gc] = rr;
        if (s == T_ - 1)
            hlast[gb * H_ + gc] = rr;

        // ---- half-scoped epilogue rendezvous + per-half flag release ----
        if (s != T_ - 1) {
            if (p == 0) {
                asm volatile("bar.sync %0, 256;" :: "r"(bar_epi) : "memory");
                if (tid_h == 0)
                    st_rel(&g_flag[group][ci][0], (unsigned)(s + 1));
            } else {
                asm volatile("bar.arrive %0, 256;" :: "r"(bar_epi) : "memory");
            }
        }
    }
}

// ---------------------------------------------------------------------------
// Kernel C: output_list[bt][o] = hid[bt]·W_out[o] + b_out[o]   (f32x2)
// 64x64 tile, 256 threads, cp.async depth-4 pipeline, FULL K (32 chunks).
// ---------------------------------------------------------------------------
#define OC 36
#define OBUF (64 * OC)

__device__ __forceinline__ void cp16(unsigned dst, const void* src) {
    asm volatile("cp.async.cg.shared.global [%0], [%1], 16;"
                 :: "r"(dst), "l"(src) : "memory");
}
__device__ __forceinline__ void cp_commit() {
    asm volatile("cp.async.commit_group;" ::: "memory");
}

__global__ void __launch_bounds__(256) out_kernel(
    const float* __restrict__ hid, const float* __restrict__ Wout,
    const float* __restrict__ bout, float* __restrict__ outp)
{
    extern __shared__ float osm[];
    float* hsA = osm;
    float* wsA = osm + 4 * OBUF;

    const int tid = threadIdx.x;
    const int btb = blockIdx.x * 64;
    const int tx = tid & 15, ty = tid >> 4;

    const float4* hid4  = (const float4*)hid;
    const float4* wout4 = (const float4*)Wout;

    const unsigned hs_base  = (unsigned)__cvta_generic_to_shared(hsA);
    const unsigned ws_base  = (unsigned)__cvta_generic_to_shared(wsA);
    const unsigned buf_step = OBUF * 4;

    auto issue = [&](int c, int b) {
        #pragma unroll
        for (int k = 0; k < 2; ++k) {
            int idx = k * 256 + tid;
            int r = idx >> 3, f = idx & 7;
            unsigned off = (unsigned)(r * OC + f * 4) * 4u + (unsigned)b * buf_step;
            cp16(hs_base + off, &hid4[(btb + r) * 256 + c * 8 + f]);
            cp16(ws_base + off, &wout4[r * 256 + c * 8 + f]);
        }
        cp_commit();
    };

    ull acc[4][4];
    #pragma unroll
    for (int i = 0; i < 4; ++i)
        #pragma unroll
        for (int j = 0; j < 4; ++j) acc[i][j] = 0ull;

    issue(0, 0); issue(1, 1); issue(2, 2); issue(3, 3);

    #pragma unroll 1
    for (int c = 0; c < 32; ++c) {
        if (c < 29)       asm volatile("cp.async.wait_group 3;" ::: "memory");
        else if (c == 29) asm volatile("cp.async.wait_group 2;" ::: "memory");
        else if (c == 30) asm volatile("cp.async.wait_group 1;" ::: "memory");
        else              asm volatile("cp.async.wait_group 0;" ::: "memory");
        __syncthreads();

        const int b = c & 3;
        const float* hb = hsA + b * OBUF;
        const float* wb = wsA + b * OBUF;

        #pragma unroll
        for (int k4 = 0; k4 < 8; ++k4) {
            ull2 a2[4], b2[4];
            #pragma unroll
            for (int i = 0; i < 4; ++i)
                a2[i] = *(const ull2*)&hb[(ty + 16 * i) * OC + k4 * 4];
            #pragma unroll
            for (int j = 0; j < 4; ++j)
                b2[j] = *(const ull2*)&wb[(tx + 16 * j) * OC + k4 * 4];
            #pragma unroll
            for (int i = 0; i < 4; ++i)
                #pragma unroll
                for (int j = 0; j < 4; ++j) {
                    acc[i][j] = f2fma(a2[i].x, b2[j].x, acc[i][j]);
                    acc[i][j] = f2fma(a2[i].y, b2[j].y, acc[i][j]);
                }
        }
        __syncthreads();

        if (c + 4 <= 31) issue(c + 4, (c + 4) & 3);
    }

    #pragma unroll
    for (int j = 0; j < 4; ++j) {
        int o = tx + 16 * j;
        float bb = bout[o];
        #pragma unroll
        for (int i = 0; i < 4; ++i)
            outp[(btb + ty + 16 * i) * O_ + o] = pairsum(acc[i][j]) + bb;
    }
}

// ---------------------------------------------------------------------------
extern "C" void kernel_launch(void* const* d_in, const int* in_sizes, int n_in,
                              void* d_out, int out_size) {
    const float* x      = (const float*)d_in[0];
    const float* hidden = (const float*)d_in[1];
    const float* W_ih   = (const float*)d_in[2];
    const float* W_hh   = (const float*)d_in[3];
    const float* b_ih   = (const float*)d_in[4];
    const float* b_hh   = (const float*)d_in[5];
    const float* W_out  = (const float*)d_in[6];
    const float* b_out  = (const float*)d_in[7];
    float* out = (float*)d_out;

    // A: 128x64 tiles, dynamic smem 50,688 B
    size_t smemA = (size_t)(128 * 66 + 64 * 66) * sizeof(float);
    cudaFuncSetAttribute(xw_kernel, cudaFuncAttributeMaxDynamicSharedMemorySize,
                         (int)smemA);
    dim3 gA(H_ / 64, (B_ * T_) / 128);
    xw_kernel<<<gA, 256, smemA>>>(x, W_ih, b_ih, b_hh, out + HID_OFF);

    // B: SMEM = 4*WQ + 2*HHALF + 2*PHALF = 34912+17440+4608 = 56960 floats
    //         = 227,840 B
    size_t smemB = (size_t)(4 * WQ + 2 * HHALF + 2 * PHALF) * sizeof(float);
    cudaFuncSetAttribute(rnn_recur, cudaFuncAttributeMaxDynamicSharedMemorySize,
                         (int)smemB);
    rnn_recur<<<NBLK, TB, smemB>>>(hidden, W_hh, out);

    // C: depth-4 pipeline, dynamic smem 73,728 B
    size_t smemC = (size_t)(8 * OBUF) * sizeof(float);
    cudaFuncSetAttribute(out_kernel, cudaFuncAttributeMaxDynamicSharedMemorySize,
                         (int)smemC);
    out_kernel<<<(B_ * T_) / 64, 256, smemC>>>(out + HID_OFF, W_out, b_out,
                                               out + OUT_OFF);
}